// round 11
// baseline (speedup 1.0000x reference)
#include <cuda_runtime.h>
#include <cstdint>

// SpikeLoss: delta = outputs - psp(target, tau=5); loss = 0.5*sum(delta^2)
// psp: syn_t = 0.8*syn_{t-1} + x_t ; y_t = syn_t/5, scan over T=100.
//
// cp.async-staged, double-buffered pipeline:
//   - warp owns 16 consecutive rows (4 tiles x 4 rows)
//   - tiles staged global->smem via cp.async.cg (no register coupling),
//     one commit_group per tile, wait_group 1 keeps next tile in flight
//     while the current tile is scanned from smem
//   - hybrid scan per row: 3-fma local scan + Kogge-Stone lane scan
//     (factor 0.8^4) + exclusive-carry fixup; accumulate only lanes <25

static constexpr int T_STEPS        = 100;
static constexpr int ROWS_PER_TILE  = 4;
static constexpr int TILES_PER_WARP = 4;
static constexpr int ROWS_PER_WARP  = ROWS_PER_TILE * TILES_PER_WARP;  // 16
static constexpr int WARPS_PER_BLOCK = 4;
static constexpr int THREADS        = WARPS_PER_BLOCK * 32;            // 128

static constexpr int ROW_BYTES      = T_STEPS * 4;                     // 400
static constexpr int TILE_T_BYTES   = ROWS_PER_TILE * ROW_BYTES;       // 1600
static constexpr int TILE_BYTES     = 2 * TILE_T_BYTES;                // 3200
static constexpr int VEC_PER_TENSOR = TILE_T_BYTES / 16;               // 100

static constexpr float DECAY   = 0.8f;
static constexpr float INV_TAU = 0.2f;
static constexpr float D4  = 0.4096f;          // 0.8^4
static constexpr float D8  = D4 * D4;
static constexpr float D16 = D8 * D8;
static constexpr float D32 = D16 * D16;
static constexpr float D64 = D32 * D32;

__device__ __forceinline__ void cp16(void* dst_smem, const void* src) {
    uint32_t d = (uint32_t)__cvta_generic_to_shared(dst_smem);
    asm volatile("cp.async.cg.shared.global [%0], [%1], 16;\n"
                 :: "r"(d), "l"(src) : "memory");
}
__device__ __forceinline__ void cp_commit() {
    asm volatile("cp.async.commit_group;\n" ::: "memory");
}
template <int N>
__device__ __forceinline__ void cp_wait() {
    asm volatile("cp.async.wait_group %0;\n" :: "n"(N) : "memory");
}

__device__ __forceinline__ float row_pass(float4 tv, float4 ov, int lane, bool ok) {
    float s0 = tv.x;
    float s1 = fmaf(DECAY, s0, tv.y);
    float s2 = fmaf(DECAY, s1, tv.z);
    float s3 = fmaf(DECAY, s2, tv.w);

    float v = s3, u;
    u = __shfl_up_sync(0xffffffffu, v, 1);
    if (lane >= 1)  v = fmaf(D4,  u, v);
    u = __shfl_up_sync(0xffffffffu, v, 2);
    if (lane >= 2)  v = fmaf(D8,  u, v);
    u = __shfl_up_sync(0xffffffffu, v, 4);
    if (lane >= 4)  v = fmaf(D16, u, v);
    u = __shfl_up_sync(0xffffffffu, v, 8);
    if (lane >= 8)  v = fmaf(D32, u, v);
    u = __shfl_up_sync(0xffffffffu, v, 16);
    if (lane >= 16) v = fmaf(D64, u, v);

    float carry = __shfl_up_sync(0xffffffffu, v, 1);
    if (lane == 0) carry = 0.0f;

    s0 = fmaf(0.8f,    carry, s0);
    s1 = fmaf(0.64f,   carry, s1);
    s2 = fmaf(0.512f,  carry, s2);
    s3 = fmaf(0.4096f, carry, s3);

    float acc = 0.0f;
    if (ok) {
        float d;
        d = fmaf(-INV_TAU, s0, ov.x); acc = fmaf(d, d, acc);
        d = fmaf(-INV_TAU, s1, ov.y); acc = fmaf(d, d, acc);
        d = fmaf(-INV_TAU, s2, ov.z); acc = fmaf(d, d, acc);
        d = fmaf(-INV_TAU, s3, ov.w); acc = fmaf(d, d, acc);
    }
    return acc;
}

__global__ __launch_bounds__(THREADS)
void spike_loss_kernel(const float* __restrict__ outputs,
                       const float* __restrict__ target,
                       float* __restrict__ out,
                       int n_rows) {
    __shared__ __align__(16) char smem_buf[WARPS_PER_BLOCK][2][TILE_BYTES];

    const int lane  = threadIdx.x & 31;
    const int wid   = threadIdx.x >> 5;
    const int gwarp = blockIdx.x * WARPS_PER_BLOCK + wid;
    const int row0  = gwarp * ROWS_PER_WARP;
    const bool ok   = (lane < 25);
    const float4 zero4 = make_float4(0.f, 0.f, 0.f, 0.f);

    float acc = 0.0f;

    int total_tiles = 0;
    if (row0 < n_rows)
        total_tiles = min(TILES_PER_WARP,
                          (n_rows - row0 + ROWS_PER_TILE - 1) / ROWS_PER_TILE);

    // stage tile: copy vrows rows of both tensors into smem stage s
    auto stage_tile = [&](int s, int tbase, int vrows) {
        const char* gt = (const char*)(target  + (size_t)tbase * T_STEPS);
        const char* go = (const char*)(outputs + (size_t)tbase * T_STEPS);
        char* st = smem_buf[wid][s];
        const int nvec = vrows * (ROW_BYTES / 16);   // <= 100
        #pragma unroll
        for (int i = 0; i < 4; ++i) {
            int idx = i * 32 + lane;
            if (idx < nvec) cp16(st + idx * 16, gt + idx * 16);
        }
        #pragma unroll
        for (int i = 0; i < 4; ++i) {
            int idx = i * 32 + lane;
            if (idx < nvec) cp16(st + TILE_T_BYTES + idx * 16, go + idx * 16);
        }
        cp_commit();
    };

    if (total_tiles > 0) {
        stage_tile(0, row0, min(ROWS_PER_TILE, n_rows - row0));

        for (int k = 0; k < total_tiles; ++k) {
            // Guard: no lane may still be reading buffer (k&1) from two
            // iterations ago when we overwrite it below.
            __syncwarp();

            const bool have_next = (k + 1 < total_tiles);
            if (have_next) {
                const int tb = row0 + (k + 1) * ROWS_PER_TILE;
                stage_tile((k + 1) & 1, tb, min(ROWS_PER_TILE, n_rows - tb));
                cp_wait<1>();
            } else {
                cp_wait<0>();
            }
            __syncwarp();

            const char* st = smem_buf[wid][k & 1];
            const int vr = min(ROWS_PER_TILE, n_rows - (row0 + k * ROWS_PER_TILE));
            #pragma unroll
            for (int r = 0; r < ROWS_PER_TILE; ++r) {
                if (r < vr) {
                    float4 tv = ok ? *reinterpret_cast<const float4*>(
                                         st + r * ROW_BYTES + lane * 16)
                                   : zero4;
                    float4 ov = ok ? *reinterpret_cast<const float4*>(
                                         st + TILE_T_BYTES + r * ROW_BYTES + lane * 16)
                                   : zero4;
                    acc += row_pass(tv, ov, lane, ok);
                }
            }
        }
    }

    // Warp reduction
    #pragma unroll
    for (int off = 16; off > 0; off >>= 1)
        acc += __shfl_down_sync(0xffffffffu, acc, off);

    __shared__ float warp_sums[WARPS_PER_BLOCK];
    if (lane == 0) warp_sums[wid] = acc;
    __syncthreads();

    if (wid == 0) {
        acc = (lane < WARPS_PER_BLOCK) ? warp_sums[lane] : 0.0f;
        #pragma unroll
        for (int off = 2; off > 0; off >>= 1)
            acc += __shfl_down_sync(0xffffffffu, acc, off);
        if (lane == 0)
            atomicAdd(out, 0.5f * acc);
    }
}

extern "C" void kernel_launch(void* const* d_in, const int* in_sizes, int n_in,
                              void* d_out, int out_size) {
    const float* outputs = (const float*)d_in[0];
    const float* target  = (const float*)d_in[1];
    float*       out     = (float*)d_out;

    const int n_elems = in_sizes[0];
    const int n_rows  = n_elems / T_STEPS;   // 131072

    cudaMemsetAsync(out, 0, sizeof(float));

    const int rows_per_block = ROWS_PER_WARP * WARPS_PER_BLOCK;   // 64
    const int blocks = (n_rows + rows_per_block - 1) / rows_per_block;  // 2048
    spike_loss_kernel<<<blocks, THREADS>>>(outputs, target, out, n_rows);
}